// round 1
// baseline (speedup 1.0000x reference)
#include <cuda_runtime.h>
#include <math.h>

#define BB   256
#define DD   1024
#define HH   8
#define HDIM 128
#define PP   2048
#define HIDD 1024
#define KW   4
#define EPSF 1e-5f

// ---------------- scratch (device globals; no allocation allowed) ----------
__device__ float g_xn [BB*DD];    // layernorm(seq)
__device__ float g_xt [BB*PP];    // up_l
__device__ float g_rt [BB*HIDD];  // up_r
__device__ float g_xc [BB*PP];    // conv+silu
__device__ float g_q  [BB*HIDD];
__device__ float g_k  [BB*HIDD];
__device__ float g_v  [BB*HIDD];
__device__ float g_o  [BB*HIDD];  // sigmoid(o)
__device__ float g_sk [BB*HIDD];  // skip
__device__ float g_i  [BB*HH];
__device__ float g_f  [BB*HH];
__device__ float g_hn [BB*HIDD];  // groupnormed h
__device__ float g_y  [BB*HIDD];  // (hn+skip)*silu(r)

// ---------------- LayerNorm: one block per row --------------------------
__global__ void ln_kernel(const float* __restrict__ x,
                          const float* __restrict__ w,
                          const float* __restrict__ b) {
    int row = blockIdx.x;
    const float* xr = x + row * DD;
    float s = 0.f, s2 = 0.f;
    for (int i = threadIdx.x; i < DD; i += blockDim.x) {
        float v = xr[i]; s += v; s2 += v * v;
    }
    __shared__ float rs[32], rs2[32];
    for (int o = 16; o; o >>= 1) {
        s  += __shfl_xor_sync(0xffffffffu, s,  o);
        s2 += __shfl_xor_sync(0xffffffffu, s2, o);
    }
    int wr = threadIdx.x >> 5, ln = threadIdx.x & 31;
    if (ln == 0) { rs[wr] = s; rs2[wr] = s2; }
    __syncthreads();
    if (wr == 0) {
        int nw = blockDim.x >> 5;
        s  = (ln < nw) ? rs[ln]  : 0.f;
        s2 = (ln < nw) ? rs2[ln] : 0.f;
        for (int o = 16; o; o >>= 1) {
            s  += __shfl_xor_sync(0xffffffffu, s,  o);
            s2 += __shfl_xor_sync(0xffffffffu, s2, o);
        }
        if (ln == 0) { rs[0] = s; rs2[0] = s2; }
    }
    __syncthreads();
    float mu  = rs[0] / (float)DD;
    float var = rs2[0] / (float)DD - mu * mu;
    float r   = rsqrtf(var + EPSF);
    for (int i = threadIdx.x; i < DD; i += blockDim.x)
        g_xn[row * DD + i] = (xr[i] - mu) * r * w[i] + b[i];
}

// ---------------- generic fp32 GEMM: Y[M,N] = X[M,Kd] @ W[N,Kd]^T ---------
// epilogue: v = (acc + bias[col]) * scale ; act==1 -> sigmoid ; resid add
__global__ void gemm_kernel(const float* __restrict__ X,
                            const float* __restrict__ W,
                            const float* __restrict__ bias,
                            float* __restrict__ Y,
                            int N, int Kd, float scale, int act,
                            const float* __restrict__ resid) {
    __shared__ float As[16][64];
    __shared__ float Ws[16][64];
    int bm = blockIdx.y * 64, bn = blockIdx.x * 64;
    int tid = threadIdx.x;
    int lr = tid >> 2;          // 0..63
    int lc = (tid & 3) * 4;     // 0,4,8,12
    float acc[4][4] = {};
    const float* Xp = X + (size_t)(bm + lr) * Kd + lc;
    const float* Wp = W + (size_t)(bn + lr) * Kd + lc;
    int ty = tid >> 4, tx = tid & 15;

    for (int k0 = 0; k0 < Kd; k0 += 16) {
        float4 a4 = *(const float4*)(Xp + k0);
        float4 w4 = *(const float4*)(Wp + k0);
        As[lc + 0][lr] = a4.x; As[lc + 1][lr] = a4.y;
        As[lc + 2][lr] = a4.z; As[lc + 3][lr] = a4.w;
        Ws[lc + 0][lr] = w4.x; Ws[lc + 1][lr] = w4.y;
        Ws[lc + 2][lr] = w4.z; Ws[lc + 3][lr] = w4.w;
        __syncthreads();
#pragma unroll
        for (int kk = 0; kk < 16; kk++) {
            float4 av = *(const float4*)&As[kk][ty * 4];
            float4 bv = *(const float4*)&Ws[kk][tx * 4];
            float a[4] = {av.x, av.y, av.z, av.w};
            float bb[4] = {bv.x, bv.y, bv.z, bv.w};
#pragma unroll
            for (int i = 0; i < 4; i++)
#pragma unroll
                for (int j = 0; j < 4; j++)
                    acc[i][j] += a[i] * bb[j];
        }
        __syncthreads();
    }
    int row = bm + ty * 4, col = bn + tx * 4;
#pragma unroll
    for (int i = 0; i < 4; i++)
#pragma unroll
        for (int j = 0; j < 4; j++) {
            float v = acc[i][j];
            if (bias) v += bias[col + j];
            v *= scale;
            if (act == 1) v = 1.f / (1.f + expf(-v));
            if (resid) v += resid[(size_t)(row + i) * N + col + j];
            Y[(size_t)(row + i) * N + col + j] = v;
        }
}

// ---------------- causal conv (K=4) along feature axis + SiLU -------------
__global__ void conv_kernel(const float* __restrict__ cw,
                            const float* __restrict__ cb) {
    int idx = blockIdx.x * blockDim.x + threadIdx.x;   // over BB*PP
    int b = idx / PP, p = idx % PP;
    const float* x = g_xt + (size_t)b * PP;
    float s = *cb;
#pragma unroll
    for (int j = 0; j < KW; j++) {
        int src = p + j - (KW - 1);
        if (src >= 0) s += cw[j] * x[src];
    }
    g_xc[idx] = s / (1.f + expf(-s));
}

// ---------------- i_t / f_t: one block per (b,h), warp0=i, warp1=f --------
__global__ void if_kernel(const float* __restrict__ Wi, const float* __restrict__ bi,
                          const float* __restrict__ Wf, const float* __restrict__ bf) {
    int bh = blockIdx.x;
    int b = bh / HH, h = bh % HH;
    int warp = threadIdx.x >> 5, lane = threadIdx.x & 31;
    const float* W = warp ? Wf : Wi;
    const float* xc = g_xc + (size_t)b * PP;
    const float* wr = W + (size_t)h * PP;
    float s = 0.f;
    for (int i = lane; i < PP; i += 32) s += xc[i] * wr[i];
    for (int o = 16; o; o >>= 1) s += __shfl_xor_sync(0xffffffffu, s, o);
    if (lane == 0) {
        if (warp) g_f[bh] = s + bf[h];
        else      g_i[bh] = s + bi[h];
    }
}

// ---------------- cell: gates, c_t, n_t, num/den, o-gate, GroupNorm -------
__global__ void cell_kernel(const float* __restrict__ c_in,
                            const float* __restrict__ n_in,
                            const float* __restrict__ m_in,
                            const float* __restrict__ gnw,
                            const float* __restrict__ gnb,
                            float* __restrict__ c_out,
                            float* __restrict__ n_out,
                            float* __restrict__ m_out) {
    int bh = blockIdx.x;
    int b = bh >> 3, h = bh & 7;
    __shared__ float sq[HDIM], sk[HDIM], sv[HDIM], sh[HDIM];
    __shared__ float s_red[16];
    __shared__ float s_ig, s_fg, s_den, s_mu, s_rstd;
    int tid = threadIdx.x;
    int warp = tid >> 5, lane = tid & 31;

    if (tid == 0) {
        float it = g_i[bh], ft = g_f[bh], m0 = m_in[bh];
        float mt = fmaxf(ft + m0, it);
        s_ig = expf(it - mt);
        s_fg = expf(ft - mt + m0);
        m_out[bh] = mt;
    }
    if (tid < HDIM) {
        int off = b * HIDD + h * HDIM + tid;
        sq[tid] = g_q[off]; sk[tid] = g_k[off]; sv[tid] = g_v[off];
    }
    __syncthreads();
    float ig = s_ig, fg = s_fg;

    // n_t and den
    float dp = 0.f;
    if (tid < HDIM) {
        float nt = fg * n_in[(size_t)bh * HDIM + tid] + ig * sk[tid];
        n_out[(size_t)bh * HDIM + tid] = nt;
        dp = nt * sq[tid];
    }
    for (int o = 16; o; o >>= 1) dp += __shfl_xor_sync(0xffffffffu, dp, o);
    if (lane == 0) s_red[warp] = dp;
    __syncthreads();
    if (tid == 0)
        s_den = fmaxf(s_red[0] + s_red[1] + s_red[2] + s_red[3], 1.0f);

    // c_t rows: 8 warps x 16 rows, one float4 per lane per row
    float4 kv = ((const float4*)sk)[lane];
    float4 qv = ((const float4*)sq)[lane];
    size_t base = (size_t)bh * HDIM * HDIM;
    for (int d = warp; d < HDIM; d += 8) {
        const float4* src = (const float4*)(c_in + base + (size_t)d * HDIM);
        float4*       dst = (float4*)(c_out + base + (size_t)d * HDIM);
        float ivd = ig * sv[d];
        float4 c = src[lane];
        float4 nc;
        nc.x = fg * c.x + ivd * kv.x;
        nc.y = fg * c.y + ivd * kv.y;
        nc.z = fg * c.z + ivd * kv.z;
        nc.w = fg * c.w + ivd * kv.w;
        dst[lane] = nc;
        float a = nc.x * qv.x + nc.y * qv.y + nc.z * qv.z + nc.w * qv.w;
        for (int o = 16; o; o >>= 1) a += __shfl_xor_sync(0xffffffffu, a, o);
        if (lane == 0) sh[d] = a;   // num[d]
    }
    __syncthreads();

    // h = o * num/den; GroupNorm over the 128 channels of this (b,h)
    float hv = 0.f;
    if (tid < HDIM)
        hv = g_o[b * HIDD + h * HDIM + tid] * sh[tid] / s_den;
    float s1 = hv, s2 = hv * hv;
    for (int o = 16; o; o >>= 1) {
        s1 += __shfl_xor_sync(0xffffffffu, s1, o);
        s2 += __shfl_xor_sync(0xffffffffu, s2, o);
    }
    if (lane == 0) { s_red[warp] = s1; s_red[8 + warp] = s2; }
    __syncthreads();
    if (tid == 0) {
        float m1 = (s_red[0] + s_red[1] + s_red[2] + s_red[3]) / (float)HDIM;
        float m2 = (s_red[8] + s_red[9] + s_red[10] + s_red[11]) / (float)HDIM;
        s_mu = m1;
        s_rstd = rsqrtf(m2 - m1 * m1 + EPSF);
    }
    __syncthreads();
    if (tid < HDIM) {
        int c = h * HDIM + tid;
        g_hn[b * HIDD + c] = (hv - s_mu) * s_rstd * gnw[c] + gnb[c];
    }
}

// ---------------- mix: y = (hn + skip) * silu(r) ---------------------------
__global__ void mix_kernel() {
    int i = blockIdx.x * blockDim.x + threadIdx.x;   // BB*HIDD
    float r = g_rt[i];
    g_y[i] = (g_hn[i] + g_sk[i]) * (r / (1.f + expf(-r)));
}

// ---------------- host launch ---------------------------------------------
static float* sym_addr(const void* sym) {
    void* p = nullptr;
    cudaGetSymbolAddress(&p, sym);
    return (float*)p;
}

extern "C" void kernel_launch(void* const* d_in, const int* in_sizes, int n_in,
                              void* d_out, int out_size) {
    const float* seq    = (const float*)d_in[0];
    const float* c_tm1  = (const float*)d_in[1];
    const float* n_tm1  = (const float*)d_in[2];
    const float* m_tm1  = (const float*)d_in[3];
    const float* ln_w   = (const float*)d_in[4];
    const float* ln_b   = (const float*)d_in[5];
    const float* gn_w   = (const float*)d_in[6];
    const float* gn_b   = (const float*)d_in[7];
    const float* up_l_w = (const float*)d_in[8];
    const float* up_l_b = (const float*)d_in[9];
    const float* up_r_w = (const float*)d_in[10];
    const float* up_r_b = (const float*)d_in[11];
    const float* down_w = (const float*)d_in[12];
    const float* down_b = (const float*)d_in[13];
    const float* Wi_w   = (const float*)d_in[14];
    const float* Wi_b   = (const float*)d_in[15];
    const float* Wf_w   = (const float*)d_in[16];
    const float* Wf_b   = (const float*)d_in[17];
    const float* Wo_w   = (const float*)d_in[18];
    const float* Wo_b   = (const float*)d_in[19];
    const float* Wq_w   = (const float*)d_in[20];
    const float* Wq_b   = (const float*)d_in[21];
    const float* Wk_w   = (const float*)d_in[22];
    const float* Wk_b   = (const float*)d_in[23];
    const float* Wv_w   = (const float*)d_in[24];
    const float* Wv_b   = (const float*)d_in[25];
    const float* conv_w = (const float*)d_in[26];
    const float* conv_b = (const float*)d_in[27];
    const float* skip_w = (const float*)d_in[28];

    float* out   = (float*)d_out;
    float* c_out = out + (size_t)BB * DD;
    float* n_out = c_out + (size_t)BB * HH * HDIM * HDIM;
    float* m_out = n_out + (size_t)BB * HH * HDIM;

    float* p_xn = sym_addr(g_xn);
    float* p_xt = sym_addr(g_xt);
    float* p_rt = sym_addr(g_rt);
    float* p_xc = sym_addr(g_xc);
    float* p_q  = sym_addr(g_q);
    float* p_k  = sym_addr(g_k);
    float* p_v  = sym_addr(g_v);
    float* p_o  = sym_addr(g_o);
    float* p_sk = sym_addr(g_sk);
    float* p_y  = sym_addr(g_y);

    const float kscale = 1.0f / sqrtf((float)HDIM);

    // 1. LayerNorm
    ln_kernel<<<BB, 256>>>(seq, ln_w, ln_b);
    // 2-3. up projections
    gemm_kernel<<<dim3(PP / 64, BB / 64), 256>>>(p_xn, up_l_w, up_l_b, p_xt, PP, DD, 1.f, 0, nullptr);
    gemm_kernel<<<dim3(HIDD / 64, BB / 64), 256>>>(p_xn, up_r_w, up_r_b, p_rt, HIDD, DD, 1.f, 0, nullptr);
    // 4. causal conv + SiLU
    conv_kernel<<<(BB * PP) / 256, 256>>>(conv_w, conv_b);
    // 5-9. projections
    gemm_kernel<<<dim3(HIDD / 64, BB / 64), 256>>>(p_xc, Wq_w, Wq_b, p_q, HIDD, PP, 1.f, 0, nullptr);
    gemm_kernel<<<dim3(HIDD / 64, BB / 64), 256>>>(p_xc, Wk_w, Wk_b, p_k, HIDD, PP, kscale, 0, nullptr);
    gemm_kernel<<<dim3(HIDD / 64, BB / 64), 256>>>(p_xt, Wv_w, Wv_b, p_v, HIDD, PP, 1.f, 0, nullptr);
    gemm_kernel<<<dim3(HIDD / 64, BB / 64), 256>>>(p_xt, Wo_w, Wo_b, p_o, HIDD, PP, 1.f, 1, nullptr);
    gemm_kernel<<<dim3(HIDD / 64, BB / 64), 256>>>(p_xc, skip_w, nullptr, p_sk, HIDD, PP, 1.f, 0, nullptr);
    // 10. i/f gates
    if_kernel<<<BB * HH, 64>>>(Wi_w, Wi_b, Wf_w, Wf_b);
    // 11. cell update + groupnorm
    cell_kernel<<<BB * HH, 256>>>(c_tm1, n_tm1, m_tm1, gn_w, gn_b, c_out, n_out, m_out);
    // 12. gated mix
    mix_kernel<<<(BB * HIDD) / 256, 256>>>();
    // 13. down projection + residual
    gemm_kernel<<<dim3(DD / 64, BB / 64), 256>>>(p_y, down_w, down_b, out, DD, HIDD, 1.f, 0, seq);
}

// round 2
// speedup vs baseline: 2.7141x; 2.7141x over previous
#include <cuda_runtime.h>
#include <math.h>

#define BB   256
#define DD   1024
#define HH   8
#define HDIM 128
#define PP   2048
#define HIDD 1024
#define KW   4
#define EPSF 1e-5f

// GEMM tiling
#define BM   64
#define BN   128
#define KT   16
#define BMs  68     // padded smem stride for A (k-major)
#define BNs  132    // padded smem stride for B (k-major)

// ---------------- scratch (device globals; no allocation allowed) ----------
__device__ float g_xn [BB*DD];    // layernorm(seq)
__device__ float g_xt [BB*PP];    // up_l
__device__ float g_rt [BB*HIDD];  // up_r
__device__ float g_xc [BB*PP];    // conv+silu
__device__ float g_q  [BB*HIDD];
__device__ float g_k  [BB*HIDD];
__device__ float g_v  [BB*HIDD];
__device__ float g_o  [BB*HIDD];  // sigmoid(o)
__device__ float g_sk [BB*HIDD];  // skip
__device__ float g_i  [BB*HH];
__device__ float g_f  [BB*HH];
__device__ float g_hn [BB*HIDD];  // groupnormed h
__device__ float g_y  [BB*HIDD];  // (hn+skip)*silu(r)
__device__ float g_part[4*BB*HIDD]; // split-K partials for down proj

// ---------------- f32x2 packed helpers (sm_103a FFMA2) ---------------------
__device__ __forceinline__ unsigned long long pk2(float x, float y) {
    unsigned long long r;
    asm("mov.b64 %0, {%1, %2};" : "=l"(r) : "f"(x), "f"(y));
    return r;
}
__device__ __forceinline__ float2 up2(unsigned long long v) {
    float2 r;
    asm("mov.b64 {%0, %1}, %2;" : "=f"(r.x), "=f"(r.y) : "l"(v));
    return r;
}
#define FMA2(d, a, b) asm("fma.rn.f32x2 %0, %1, %2, %0;" : "+l"(d) : "l"(a), "l"(b))

// ---------------- LayerNorm: one block per row ------------------------------
__global__ void ln_kernel(const float* __restrict__ x,
                          const float* __restrict__ w,
                          const float* __restrict__ b) {
    int row = blockIdx.x;
    const float* xr = x + row * DD;
    float s = 0.f, s2 = 0.f;
    for (int i = threadIdx.x; i < DD; i += blockDim.x) {
        float v = xr[i]; s += v; s2 += v * v;
    }
    __shared__ float rs[32], rs2[32];
    for (int o = 16; o; o >>= 1) {
        s  += __shfl_xor_sync(0xffffffffu, s,  o);
        s2 += __shfl_xor_sync(0xffffffffu, s2, o);
    }
    int wr = threadIdx.x >> 5, ln = threadIdx.x & 31;
    if (ln == 0) { rs[wr] = s; rs2[wr] = s2; }
    __syncthreads();
    if (wr == 0) {
        int nw = blockDim.x >> 5;
        s  = (ln < nw) ? rs[ln]  : 0.f;
        s2 = (ln < nw) ? rs2[ln] : 0.f;
        for (int o = 16; o; o >>= 1) {
            s  += __shfl_xor_sync(0xffffffffu, s,  o);
            s2 += __shfl_xor_sync(0xffffffffu, s2, o);
        }
        if (ln == 0) { rs[0] = s; rs2[0] = s2; }
    }
    __syncthreads();
    float mu  = rs[0] / (float)DD;
    float var = rs2[0] / (float)DD - mu * mu;
    float r   = rsqrtf(var + EPSF);
    for (int i = threadIdx.x; i < DD; i += blockDim.x)
        g_xn[row * DD + i] = (xr[i] - mu) * r * w[i] + b[i];
}

// ---------------- multi-segment FFMA2 GEMM ---------------------------------
// Y[M, Nseg] = X[M, K] @ W[Nseg, K]^T, epilogue (acc+bias)*scale, opt sigmoid
struct GemmSeg {
    const float* X; const float* W; const float* bias; float* Y;
    float scale; int act; int nblkN; int Nseg;
};
struct GemmArgs { GemmSeg s[5]; int nseg; int K; };

__global__ __launch_bounds__(256, 1)
void gemm_multi(GemmArgs args) {
    int nb = blockIdx.x;
    int si = 0;
    while (si < args.nseg - 1 && nb >= args.s[si].nblkN) { nb -= args.s[si].nblkN; si++; }
    const GemmSeg sg = args.s[si];
    const int K = args.K;
    const int bm = blockIdx.y * BM;

    __shared__ float As[KT * BMs];
    __shared__ float Bs[KT * BNs];

    int tid = threadIdx.x;
    int lr = tid >> 2, lc = tid & 3;          // loader: row 0..63, col-chunk 0..3
    int ty = tid >> 4, tx = tid & 15;         // compute: 16x16

    const float* Xp  = sg.X + (size_t)(bm + lr) * K + lc * 4;
    const float* Wp0 = sg.W + (size_t)(nb * BN + lr) * K + lc * 4;
    const float* Wp1 = Wp0 + (size_t)64 * K;

    unsigned long long acc[4][4];
#pragma unroll
    for (int i = 0; i < 4; i++)
#pragma unroll
        for (int j = 0; j < 4; j++) acc[i][j] = 0ULL;

    float4 ra  = *(const float4*)Xp;
    float4 rb0 = *(const float4*)Wp0;
    float4 rb1 = *(const float4*)Wp1;

    const int ktiles = K / KT;
    for (int t = 0; t < ktiles; t++) {
        As[(lc * 4 + 0) * BMs + lr] = ra.x;
        As[(lc * 4 + 1) * BMs + lr] = ra.y;
        As[(lc * 4 + 2) * BMs + lr] = ra.z;
        As[(lc * 4 + 3) * BMs + lr] = ra.w;
        Bs[(lc * 4 + 0) * BNs + lr] = rb0.x;
        Bs[(lc * 4 + 1) * BNs + lr] = rb0.y;
        Bs[(lc * 4 + 2) * BNs + lr] = rb0.z;
        Bs[(lc * 4 + 3) * BNs + lr] = rb0.w;
        Bs[(lc * 4 + 0) * BNs + lr + 64] = rb1.x;
        Bs[(lc * 4 + 1) * BNs + lr + 64] = rb1.y;
        Bs[(lc * 4 + 2) * BNs + lr + 64] = rb1.z;
        Bs[(lc * 4 + 3) * BNs + lr + 64] = rb1.w;
        __syncthreads();
        if (t + 1 < ktiles) {
            ra  = *(const float4*)(Xp  + (t + 1) * KT);
            rb0 = *(const float4*)(Wp0 + (t + 1) * KT);
            rb1 = *(const float4*)(Wp1 + (t + 1) * KT);
        }
#pragma unroll
        for (int kk = 0; kk < KT; kk++) {
            float4 av = *(const float4*)&As[kk * BMs + ty * 4];
            unsigned long long a0 = pk2(av.x, av.x);
            unsigned long long a1 = pk2(av.y, av.y);
            unsigned long long a2 = pk2(av.z, av.z);
            unsigned long long a3 = pk2(av.w, av.w);
            unsigned long long b0 = *(const unsigned long long*)&Bs[kk * BNs + tx * 4];
            unsigned long long b1 = *(const unsigned long long*)&Bs[kk * BNs + tx * 4 + 2];
            unsigned long long b2 = *(const unsigned long long*)&Bs[kk * BNs + tx * 4 + 64];
            unsigned long long b3 = *(const unsigned long long*)&Bs[kk * BNs + tx * 4 + 66];
            FMA2(acc[0][0], a0, b0); FMA2(acc[0][1], a0, b1);
            FMA2(acc[0][2], a0, b2); FMA2(acc[0][3], a0, b3);
            FMA2(acc[1][0], a1, b0); FMA2(acc[1][1], a1, b1);
            FMA2(acc[1][2], a1, b2); FMA2(acc[1][3], a1, b3);
            FMA2(acc[2][0], a2, b0); FMA2(acc[2][1], a2, b1);
            FMA2(acc[2][2], a2, b2); FMA2(acc[2][3], a2, b3);
            FMA2(acc[3][0], a3, b0); FMA2(acc[3][1], a3, b1);
            FMA2(acc[3][2], a3, b2); FMA2(acc[3][3], a3, b3);
        }
        __syncthreads();
    }

    // epilogue
    int c0 = nb * BN + tx * 4;
    int c1 = c0 + 64;
#pragma unroll
    for (int i = 0; i < 4; i++) {
        int row = bm + ty * 4 + i;
        float f[8];
        float2 p;
        p = up2(acc[i][0]); f[0] = p.x; f[1] = p.y;
        p = up2(acc[i][1]); f[2] = p.x; f[3] = p.y;
        p = up2(acc[i][2]); f[4] = p.x; f[5] = p.y;
        p = up2(acc[i][3]); f[6] = p.x; f[7] = p.y;
#pragma unroll
        for (int j = 0; j < 4; j++) {
            if (sg.bias) { f[j] += sg.bias[c0 + j]; f[4 + j] += sg.bias[c1 + j]; }
            f[j]     *= sg.scale;
            f[4 + j] *= sg.scale;
            if (sg.act == 1) {
                f[j]     = 1.f / (1.f + expf(-f[j]));
                f[4 + j] = 1.f / (1.f + expf(-f[4 + j]));
            }
        }
        *(float4*)&sg.Y[(size_t)row * sg.Nseg + c0] = make_float4(f[0], f[1], f[2], f[3]);
        *(float4*)&sg.Y[(size_t)row * sg.Nseg + c1] = make_float4(f[4], f[5], f[6], f[7]);
    }
}

// ---------------- split-K GEMM for down projection --------------------------
// part[kc] += X[M,1024] chunk @ W[1024,1024]^T chunk, K-chunk = 256
__global__ __launch_bounds__(256, 1)
void gemm_splitk(const float* __restrict__ X, const float* __restrict__ W) {
    const int K = HIDD;
    const int kbase = blockIdx.z * 256;
    const int nb = blockIdx.x;
    const int bm = blockIdx.y * BM;

    __shared__ float As[KT * BMs];
    __shared__ float Bs[KT * BNs];

    int tid = threadIdx.x;
    int lr = tid >> 2, lc = tid & 3;
    int ty = tid >> 4, tx = tid & 15;

    const float* Xp  = X + (size_t)(bm + lr) * K + kbase + lc * 4;
    const float* Wp0 = W + (size_t)(nb * BN + lr) * K + kbase + lc * 4;
    const float* Wp1 = Wp0 + (size_t)64 * K;

    unsigned long long acc[4][4];
#pragma unroll
    for (int i = 0; i < 4; i++)
#pragma unroll
        for (int j = 0; j < 4; j++) acc[i][j] = 0ULL;

    float4 ra  = *(const float4*)Xp;
    float4 rb0 = *(const float4*)Wp0;
    float4 rb1 = *(const float4*)Wp1;

    const int ktiles = 256 / KT;
    for (int t = 0; t < ktiles; t++) {
        As[(lc * 4 + 0) * BMs + lr] = ra.x;
        As[(lc * 4 + 1) * BMs + lr] = ra.y;
        As[(lc * 4 + 2) * BMs + lr] = ra.z;
        As[(lc * 4 + 3) * BMs + lr] = ra.w;
        Bs[(lc * 4 + 0) * BNs + lr] = rb0.x;
        Bs[(lc * 4 + 1) * BNs + lr] = rb0.y;
        Bs[(lc * 4 + 2) * BNs + lr] = rb0.z;
        Bs[(lc * 4 + 3) * BNs + lr] = rb0.w;
        Bs[(lc * 4 + 0) * BNs + lr + 64] = rb1.x;
        Bs[(lc * 4 + 1) * BNs + lr + 64] = rb1.y;
        Bs[(lc * 4 + 2) * BNs + lr + 64] = rb1.z;
        Bs[(lc * 4 + 3) * BNs + lr + 64] = rb1.w;
        __syncthreads();
        if (t + 1 < ktiles) {
            ra  = *(const float4*)(Xp  + (t + 1) * KT);
            rb0 = *(const float4*)(Wp0 + (t + 1) * KT);
            rb1 = *(const float4*)(Wp1 + (t + 1) * KT);
        }
#pragma unroll
        for (int kk = 0; kk < KT; kk++) {
            float4 av = *(const float4*)&As[kk * BMs + ty * 4];
            unsigned long long a0 = pk2(av.x, av.x);
            unsigned long long a1 = pk2(av.y, av.y);
            unsigned long long a2 = pk2(av.z, av.z);
            unsigned long long a3 = pk2(av.w, av.w);
            unsigned long long b0 = *(const unsigned long long*)&Bs[kk * BNs + tx * 4];
            unsigned long long b1 = *(const unsigned long long*)&Bs[kk * BNs + tx * 4 + 2];
            unsigned long long b2 = *(const unsigned long long*)&Bs[kk * BNs + tx * 4 + 64];
            unsigned long long b3 = *(const unsigned long long*)&Bs[kk * BNs + tx * 4 + 66];
            FMA2(acc[0][0], a0, b0); FMA2(acc[0][1], a0, b1);
            FMA2(acc[0][2], a0, b2); FMA2(acc[0][3], a0, b3);
            FMA2(acc[1][0], a1, b0); FMA2(acc[1][1], a1, b1);
            FMA2(acc[1][2], a1, b2); FMA2(acc[1][3], a1, b3);
            FMA2(acc[2][0], a2, b0); FMA2(acc[2][1], a2, b1);
            FMA2(acc[2][2], a2, b2); FMA2(acc[2][3], a2, b3);
            FMA2(acc[3][0], a3, b0); FMA2(acc[3][1], a3, b1);
            FMA2(acc[3][2], a3, b2); FMA2(acc[3][3], a3, b3);
        }
        __syncthreads();
    }

    float* part = g_part + (size_t)blockIdx.z * BB * HIDD;
    int c0 = nb * BN + tx * 4;
    int c1 = c0 + 64;
#pragma unroll
    for (int i = 0; i < 4; i++) {
        int row = bm + ty * 4 + i;
        float2 p0 = up2(acc[i][0]), p1 = up2(acc[i][1]);
        float2 p2 = up2(acc[i][2]), p3 = up2(acc[i][3]);
        *(float4*)&part[(size_t)row * HIDD + c0] = make_float4(p0.x, p0.y, p1.x, p1.y);
        *(float4*)&part[(size_t)row * HIDD + c1] = make_float4(p2.x, p2.y, p3.x, p3.y);
    }
}

// ---------------- down reduce: sum partials + bias + residual --------------
__global__ void down_reduce(const float* __restrict__ bias,
                            const float* __restrict__ seq,
                            float* __restrict__ out) {
    int i = blockIdx.x * blockDim.x + threadIdx.x;
    int col = i & (HIDD - 1);
    float v = g_part[i] + g_part[i + BB * HIDD]
            + g_part[i + 2 * BB * HIDD] + g_part[i + 3 * BB * HIDD];
    out[i] = v + bias[col] + seq[i];
}

// ---------------- causal conv (K=4) along feature axis + SiLU --------------
__global__ void conv_kernel(const float* __restrict__ cw,
                            const float* __restrict__ cb) {
    int idx = blockIdx.x * blockDim.x + threadIdx.x;
    int b = idx / PP, p = idx % PP;
    const float* x = g_xt + (size_t)b * PP;
    float s = *cb;
#pragma unroll
    for (int j = 0; j < KW; j++) {
        int src = p + j - (KW - 1);
        if (src >= 0) s += cw[j] * x[src];
    }
    g_xc[idx] = s / (1.f + expf(-s));
}

// ---------------- i_t / f_t: one block per (b,h), warp0=i, warp1=f ---------
__global__ void if_kernel(const float* __restrict__ Wi, const float* __restrict__ bi,
                          const float* __restrict__ Wf, const float* __restrict__ bf) {
    int bh = blockIdx.x;
    int b = bh / HH, h = bh % HH;
    int warp = threadIdx.x >> 5, lane = threadIdx.x & 31;
    const float* W = warp ? Wf : Wi;
    const float* xc = g_xc + (size_t)b * PP;
    const float* wr = W + (size_t)h * PP;
    float s = 0.f;
    for (int i = lane; i < PP; i += 32) s += xc[i] * wr[i];
    for (int o = 16; o; o >>= 1) s += __shfl_xor_sync(0xffffffffu, s, o);
    if (lane == 0) {
        if (warp) g_f[bh] = s + bf[h];
        else      g_i[bh] = s + bi[h];
    }
}

// ---------------- cell: gates, c_t, n_t, num/den, o-gate, GroupNorm --------
__global__ void cell_kernel(const float* __restrict__ c_in,
                            const float* __restrict__ n_in,
                            const float* __restrict__ m_in,
                            const float* __restrict__ gnw,
                            const float* __restrict__ gnb,
                            float* __restrict__ c_out,
                            float* __restrict__ n_out,
                            float* __restrict__ m_out) {
    int bh = blockIdx.x;
    int b = bh >> 3, h = bh & 7;
    __shared__ float sq[HDIM], sk[HDIM], sv[HDIM], sh[HDIM];
    __shared__ float s_red[16];
    __shared__ float s_ig, s_fg, s_den, s_mu, s_rstd;
    int tid = threadIdx.x;
    int warp = tid >> 5, lane = tid & 31;

    if (tid == 0) {
        float it = g_i[bh], ft = g_f[bh], m0 = m_in[bh];
        float mt = fmaxf(ft + m0, it);
        s_ig = expf(it - mt);
        s_fg = expf(ft - mt + m0);
        m_out[bh] = mt;
    }
    if (tid < HDIM) {
        int off = b * HIDD + h * HDIM + tid;
        sq[tid] = g_q[off]; sk[tid] = g_k[off]; sv[tid] = g_v[off];
    }
    __syncthreads();
    float ig = s_ig, fg = s_fg;

    float dp = 0.f;
    if (tid < HDIM) {
        float nt = fg * n_in[(size_t)bh * HDIM + tid] + ig * sk[tid];
        n_out[(size_t)bh * HDIM + tid] = nt;
        dp = nt * sq[tid];
    }
    for (int o = 16; o; o >>= 1) dp += __shfl_xor_sync(0xffffffffu, dp, o);
    if (lane == 0) s_red[warp] = dp;
    __syncthreads();
    if (tid == 0)
        s_den = fmaxf(s_red[0] + s_red[1] + s_red[2] + s_red[3], 1.0f);

    float4 kv = ((const float4*)sk)[lane];
    float4 qv = ((const float4*)sq)[lane];
    size_t base = (size_t)bh * HDIM * HDIM;
    for (int d = warp; d < HDIM; d += 8) {
        const float4* src = (const float4*)(c_in + base + (size_t)d * HDIM);
        float4*       dst = (float4*)(c_out + base + (size_t)d * HDIM);
        float ivd = ig * sv[d];
        float4 c = src[lane];
        float4 nc;
        nc.x = fg * c.x + ivd * kv.x;
        nc.y = fg * c.y + ivd * kv.y;
        nc.z = fg * c.z + ivd * kv.z;
        nc.w = fg * c.w + ivd * kv.w;
        dst[lane] = nc;
        float a = nc.x * qv.x + nc.y * qv.y + nc.z * qv.z + nc.w * qv.w;
        for (int o = 16; o; o >>= 1) a += __shfl_xor_sync(0xffffffffu, a, o);
        if (lane == 0) sh[d] = a;
    }
    __syncthreads();

    float hv = 0.f;
    if (tid < HDIM)
        hv = g_o[b * HIDD + h * HDIM + tid] * sh[tid] / s_den;
    float s1 = hv, s2 = hv * hv;
    for (int o = 16; o; o >>= 1) {
        s1 += __shfl_xor_sync(0xffffffffu, s1, o);
        s2 += __shfl_xor_sync(0xffffffffu, s2, o);
    }
    if (lane == 0) { s_red[warp] = s1; s_red[8 + warp] = s2; }
    __syncthreads();
    if (tid == 0) {
        float m1 = (s_red[0] + s_red[1] + s_red[2] + s_red[3]) / (float)HDIM;
        float m2 = (s_red[8] + s_red[9] + s_red[10] + s_red[11]) / (float)HDIM;
        s_mu = m1;
        s_rstd = rsqrtf(m2 - m1 * m1 + EPSF);
    }
    __syncthreads();
    if (tid < HDIM) {
        int c = h * HDIM + tid;
        g_hn[b * HIDD + c] = (hv - s_mu) * s_rstd * gnw[c] + gnb[c];
    }
}

// ---------------- mix: y = (hn + skip) * silu(r) ----------------------------
__global__ void mix_kernel() {
    int i = blockIdx.x * blockDim.x + threadIdx.x;
    float r = g_rt[i];
    g_y[i] = (g_hn[i] + g_sk[i]) * (r / (1.f + expf(-r)));
}

// ---------------- host launch -----------------------------------------------
static float* sym_addr(const void* sym) {
    void* p = nullptr;
    cudaGetSymbolAddress(&p, sym);
    return (float*)p;
}

extern "C" void kernel_launch(void* const* d_in, const int* in_sizes, int n_in,
                              void* d_out, int out_size) {
    const float* seq    = (const float*)d_in[0];
    const float* c_tm1  = (const float*)d_in[1];
    const float* n_tm1  = (const float*)d_in[2];
    const float* m_tm1  = (const float*)d_in[3];
    const float* ln_w   = (const float*)d_in[4];
    const float* ln_b   = (const float*)d_in[5];
    const float* gn_w   = (const float*)d_in[6];
    const float* gn_b   = (const float*)d_in[7];
    const float* up_l_w = (const float*)d_in[8];
    const float* up_l_b = (const float*)d_in[9];
    const float* up_r_w = (const float*)d_in[10];
    const float* up_r_b = (const float*)d_in[11];
    const float* down_w = (const float*)d_in[12];
    const float* down_b = (const float*)d_in[13];
    const float* Wi_w   = (const float*)d_in[14];
    const float* Wi_b   = (const float*)d_in[15];
    const float* Wf_w   = (const float*)d_in[16];
    const float* Wf_b   = (const float*)d_in[17];
    const float* Wo_w   = (const float*)d_in[18];
    const float* Wo_b   = (const float*)d_in[19];
    const float* Wq_w   = (const float*)d_in[20];
    const float* Wq_b   = (const float*)d_in[21];
    const float* Wk_w   = (const float*)d_in[22];
    const float* Wk_b   = (const float*)d_in[23];
    const float* Wv_w   = (const float*)d_in[24];
    const float* Wv_b   = (const float*)d_in[25];
    const float* conv_w = (const float*)d_in[26];
    const float* conv_b = (const float*)d_in[27];
    const float* skip_w = (const float*)d_in[28];

    float* out   = (float*)d_out;
    float* c_out = out + (size_t)BB * DD;
    float* n_out = c_out + (size_t)BB * HH * HDIM * HDIM;
    float* m_out = n_out + (size_t)BB * HH * HDIM;

    float* p_xn = sym_addr(g_xn);
    float* p_xt = sym_addr(g_xt);
    float* p_rt = sym_addr(g_rt);
    float* p_xc = sym_addr(g_xc);
    float* p_q  = sym_addr(g_q);
    float* p_k  = sym_addr(g_k);
    float* p_v  = sym_addr(g_v);
    float* p_o  = sym_addr(g_o);
    float* p_sk = sym_addr(g_sk);
    float* p_y  = sym_addr(g_y);

    const float kscale = 1.0f / sqrtf((float)HDIM);

    // 1. LayerNorm
    ln_kernel<<<BB, 256>>>(seq, ln_w, ln_b);

    // 2. stage1: up_l + up_r in one launch
    {
        GemmArgs a;
        a.nseg = 2; a.K = DD;
        a.s[0] = { p_xn, up_l_w, up_l_b, p_xt, 1.f, 0, PP / BN,   PP   };
        a.s[1] = { p_xn, up_r_w, up_r_b, p_rt, 1.f, 0, HIDD / BN, HIDD };
        a.s[2] = a.s[1]; a.s[3] = a.s[1]; a.s[4] = a.s[1];
        gemm_multi<<<dim3(PP / BN + HIDD / BN, BB / BM), 256>>>(a);
    }

    // 3. causal conv + SiLU
    conv_kernel<<<(BB * PP) / 256, 256>>>(conv_w, conv_b);

    // 4. stage2: q, k, v, o, skip in one launch
    {
        GemmArgs a;
        a.nseg = 5; a.K = PP;
        a.s[0] = { p_xc, Wq_w,   Wq_b,    p_q,  1.f,    0, HIDD / BN, HIDD };
        a.s[1] = { p_xc, Wk_w,   Wk_b,    p_k,  kscale, 0, HIDD / BN, HIDD };
        a.s[2] = { p_xt, Wv_w,   Wv_b,    p_v,  1.f,    0, HIDD / BN, HIDD };
        a.s[3] = { p_xt, Wo_w,   Wo_b,    p_o,  1.f,    1, HIDD / BN, HIDD };
        a.s[4] = { p_xc, skip_w, nullptr, p_sk, 1.f,    0, HIDD / BN, HIDD };
        gemm_multi<<<dim3(5 * (HIDD / BN), BB / BM), 256>>>(a);
    }

    // 5. i/f gates
    if_kernel<<<BB * HH, 64>>>(Wi_w, Wi_b, Wf_w, Wf_b);

    // 6. cell update + groupnorm
    cell_kernel<<<BB * HH, 256>>>(c_tm1, n_tm1, m_tm1, gn_w, gn_b, c_out, n_out, m_out);

    // 7. gated mix
    mix_kernel<<<(BB * HIDD) / 256, 256>>>();

    // 8. down projection (split-K=4) + reduce with bias + residual
    gemm_splitk<<<dim3(HIDD / BN, BB / BM, 4), 256>>>(p_y, down_w);
    down_reduce<<<(BB * HIDD) / 256, 256>>>(down_b, seq, out);
}

// round 5
// speedup vs baseline: 4.0457x; 1.4906x over previous
#include <cuda_runtime.h>
#include <cuda_bf16.h>
#include <cstdint>
#include <math.h>

#define BB   256
#define DD   1024
#define HH   8
#define HDIM 128
#define PP   2048
#define HIDD 1024
#define KW   4
#define EPSF 1e-5f

// mma.sync GEMM tiling
#define TBM  128
#define TBN  64
#define TBK  32
// smem per stage: AH 8192, AL 8192, BH 4096, BL 4096
#define SOFF_AH 0
#define SOFF_AL 8192
#define SOFF_BH 16384
#define SOFF_BL 20480
#define STAGE_B 24576
#define DYN_SMEM (2*STAGE_B + 128)

// ---------------- scratch (device globals; no allocation allowed) ----------
__device__ float g_xn [BB*DD];
__device__ float g_xt [BB*PP];
__device__ float g_rt [BB*HIDD];
__device__ float g_xc [BB*PP];
__device__ float g_q  [BB*HIDD];
__device__ float g_k  [BB*HIDD];
__device__ float g_v  [BB*HIDD];
__device__ float g_o  [BB*HIDD];
__device__ float g_sk [BB*HIDD];
__device__ float g_i  [BB*HH];
__device__ float g_f  [BB*HH];
__device__ float g_hn [BB*HIDD];
__device__ float g_y  [BB*HIDD];

// bf16 hi/lo splits (16B-aligned for cp.async)
#define WTOT 14680064
__device__ __align__(256) __nv_bfloat16 g_wh[WTOT];
__device__ __align__(256) __nv_bfloat16 g_wl[WTOT];
__device__ __align__(256) __nv_bfloat16 g_xnh[BB*DD],  g_xnl[BB*DD];
__device__ __align__(256) __nv_bfloat16 g_xth[BB*PP],  g_xtl[BB*PP];
__device__ __align__(256) __nv_bfloat16 g_xch[BB*PP],  g_xcl[BB*PP];
__device__ __align__(256) __nv_bfloat16 g_yh [BB*HIDD], g_yl[BB*HIDD];

// weight offsets (elements) in g_wh/g_wl
#define OFF_UPL  0u
#define OFF_UPR  2097152u
#define OFF_Q    3145728u
#define OFF_K    5242880u
#define OFF_V    7340032u
#define OFF_O    9437184u
#define OFF_SKIP 11534336u
#define OFF_DOWN 13631488u

// ---------------- PTX helpers ----------------------------------------------
__device__ __forceinline__ uint32_t smem_u32(const void* p) {
    uint32_t a;
    asm("{ .reg .u64 t; cvta.to.shared.u64 t, %1; cvt.u32.u64 %0, t; }" : "=r"(a) : "l"(p));
    return a;
}
__device__ __forceinline__ void cp16(uint32_t dst, const void* src) {
    asm volatile("cp.async.cg.shared.global [%0], [%1], 16;" :: "r"(dst), "l"(src));
}
#define CP_COMMIT() asm volatile("cp.async.commit_group;" ::: "memory")
#define CP_WAIT1()  asm volatile("cp.async.wait_group 1;" ::: "memory")
#define CP_WAIT0()  asm volatile("cp.async.wait_group 0;" ::: "memory")

__device__ __forceinline__ void ldsm4(uint32_t* r, uint32_t addr) {
    asm volatile("ldmatrix.sync.aligned.m8n8.x4.shared.b16 {%0,%1,%2,%3}, [%4];"
                 : "=r"(r[0]), "=r"(r[1]), "=r"(r[2]), "=r"(r[3]) : "r"(addr));
}
__device__ __forceinline__ void mma16816(float* c, const uint32_t* a, uint32_t b0, uint32_t b1) {
    asm volatile(
        "mma.sync.aligned.m16n8k16.row.col.f32.bf16.bf16.f32 "
        "{%0,%1,%2,%3}, {%4,%5,%6,%7}, {%8,%9}, {%0,%1,%2,%3};"
        : "+f"(c[0]), "+f"(c[1]), "+f"(c[2]), "+f"(c[3])
        : "r"(a[0]), "r"(a[1]), "r"(a[2]), "r"(a[3]), "r"(b0), "r"(b1));
}

// chunk-XOR swizzle: 64B rows, 4 chunks of 16B, conflict-free for ldmatrix
__device__ __forceinline__ uint32_t swz(int r, int c) {
    return (uint32_t)(r * 64 + ((c ^ ((r >> 1) & 3)) * 16));
}

// ---------------- tensor GEMM (mma.sync bf16 x3-split) ----------------------
struct TSeg {
    const __nv_bfloat16 *Xh, *Xl;   // [M, K]
    const __nv_bfloat16 *Wh, *Wl;   // [N, K]
    const float* bias;
    const float* resid;
    float* Y;
    float scale;
    int act;      // 1 = sigmoid
    int nblk;     // N / TBN
    int N;
};
struct TArgs { TSeg s[5]; int nseg; int K; };

__device__ __forceinline__ void load_stage(uint32_t sb,
        const __nv_bfloat16* axh, const __nv_bfloat16* axl,
        const __nv_bfloat16* bwh, const __nv_bfloat16* bwl,
        int K, int kbase, int tid) {
    // A: 128 rows x 4 chunks = 512 chunk loads per operand
#pragma unroll
    for (int i = 0; i < 2; i++) {
        int idx = tid + 256 * i;
        int row = idx >> 2, c = idx & 3;
        uint32_t o = swz(row, c);
        const size_t g = (size_t)row * K + kbase + c * 8;
        cp16(sb + SOFF_AH + o, axh + g);
        cp16(sb + SOFF_AL + o, axl + g);
    }
    // B: 64 rows x 4 chunks = 256 chunk loads per operand
    {
        int row = tid >> 2, c = tid & 3;
        uint32_t o = swz(row, c);
        const size_t g = (size_t)row * K + kbase + c * 8;
        cp16(sb + SOFF_BH + o, bwh + g);
        cp16(sb + SOFF_BL + o, bwl + g);
    }
}

__global__ __launch_bounds__(256)
void tgemm(TArgs args) {
    extern __shared__ char dyn[];
    uint32_t sb = smem_u32(dyn);
    sb = (sb + 127) & ~127u;

    // resolve segment
    int nb = blockIdx.x, si = 0;
    while (si < args.nseg - 1 && nb >= args.s[si].nblk) { nb -= args.s[si].nblk; si++; }
    const TSeg sg = args.s[si];
    const int K = args.K;
    const int bm = blockIdx.y;

    int tid = threadIdx.x;
    int wid = tid >> 5, lane = tid & 31;
    int wm = wid & 3, wn = wid >> 2;          // warp grid 4(m) x 2(n)

    const __nv_bfloat16* axh = sg.Xh + (size_t)bm * TBM * K;
    const __nv_bfloat16* axl = sg.Xl + (size_t)bm * TBM * K;
    const __nv_bfloat16* bwh = sg.Wh + (size_t)nb * TBN * K;
    const __nv_bfloat16* bwl = sg.Wl + (size_t)nb * TBN * K;

    float acc[2][4][4];
#pragma unroll
    for (int i = 0; i < 2; i++)
#pragma unroll
        for (int j = 0; j < 4; j++)
#pragma unroll
            for (int l = 0; l < 4; l++) acc[i][j][l] = 0.f;

    const int T = K / TBK;

    load_stage(sb, axh, axl, bwh, bwl, K, 0, tid);
    CP_COMMIT();

    int lr = lane & 15, lch = lane >> 4;

    for (int t = 0; t < T; t++) {
        uint32_t cur = sb + (t & 1) * STAGE_B;
        if (t + 1 < T) {
            load_stage(sb + ((t + 1) & 1) * STAGE_B, axh, axl, bwh, bwl, K, (t + 1) * TBK, tid);
            CP_COMMIT();
            CP_WAIT1();
        } else {
            CP_WAIT0();
        }
        __syncthreads();

#pragma unroll
        for (int kk = 0; kk < 2; kk++) {
            // A fragments: 2 m16 tiles, hi+lo
            uint32_t Ah[2][4], Al[2][4];
#pragma unroll
            for (int im = 0; im < 2; im++) {
                int r = wm * 32 + im * 16 + lr;
                int c = kk * 2 + lch;
                uint32_t o = swz(r, c);
                ldsm4(Ah[im], cur + SOFF_AH + o);
                ldsm4(Al[im], cur + SOFF_AL + o);
            }
            // B fragments: 2 x (n16) tiles covering n0-31 of this warp, hi+lo
            uint32_t Bh[2][4], Bl[2][4];
#pragma unroll
            for (int jn = 0; jn < 2; jn++) {
                int r = wn * 32 + jn * 16 + lr;
                int c = kk * 2 + lch;
                uint32_t o = swz(r, c);
                ldsm4(Bh[jn], cur + SOFF_BH + o);
                ldsm4(Bl[jn], cur + SOFF_BL + o);
            }
            // 2m x 4n x 3 products
#pragma unroll
            for (int im = 0; im < 2; im++) {
#pragma unroll
                for (int inn = 0; inn < 4; inn++) {
                    int jn = inn >> 1, hb = inn & 1;   // x4 group, n8 half
                    uint32_t b0h = Bh[jn][hb],     b1h = Bh[jn][hb + 2];
                    uint32_t b0l = Bl[jn][hb],     b1l = Bl[jn][hb + 2];
                    mma16816(acc[im][inn], Ah[im], b0h, b1h);
                    mma16816(acc[im][inn], Al[im], b0h, b1h);
                    mma16816(acc[im][inn], Ah[im], b0l, b1l);
                }
            }
        }
        __syncthreads();
    }

    // epilogue
    int group = lane >> 2, tig = lane & 3;
#pragma unroll
    for (int im = 0; im < 2; im++) {
#pragma unroll
        for (int inn = 0; inn < 4; inn++) {
            int mrow = bm * TBM + wm * 32 + im * 16 + group;
            int col  = nb * TBN + wn * 32 + inn * 8 + tig * 2;
#pragma unroll
            for (int half = 0; half < 2; half++) {
                int row = mrow + half * 8;
                float2 v;
                v.x = acc[im][inn][half * 2 + 0];
                v.y = acc[im][inn][half * 2 + 1];
                if (sg.bias) { v.x += sg.bias[col]; v.y += sg.bias[col + 1]; }
                v.x *= sg.scale; v.y *= sg.scale;
                if (sg.act == 1) {
                    v.x = 1.f / (1.f + expf(-v.x));
                    v.y = 1.f / (1.f + expf(-v.y));
                }
                if (sg.resid) {
                    const float2 rv = *(const float2*)&sg.resid[(size_t)row * sg.N + col];
                    v.x += rv.x; v.y += rv.y;
                }
                *(float2*)&sg.Y[(size_t)row * sg.N + col] = v;
            }
        }
    }
}

// ---------------- fp32 -> bf16 hi/lo split ----------------------------------
struct SSeg { const float* src; __nv_bfloat16* hi; __nv_bfloat16* lo; int nblk; };
struct SArgs { SSeg s[8]; int nseg; };

__global__ void split_kernel(SArgs a) {
    int b = blockIdx.x, si = 0;
    while (si < a.nseg - 1 && b >= a.s[si].nblk) { b -= a.s[si].nblk; si++; }
    const SSeg sg = a.s[si];
    int i = b * 256 + threadIdx.x;          // index of float4
    float4 v = ((const float4*)sg.src)[i];
    __nv_bfloat16 h0 = __float2bfloat16(v.x);
    __nv_bfloat16 h1 = __float2bfloat16(v.y);
    __nv_bfloat16 h2 = __float2bfloat16(v.z);
    __nv_bfloat16 h3 = __float2bfloat16(v.w);
    __nv_bfloat16 l0 = __float2bfloat16(v.x - __bfloat162float(h0));
    __nv_bfloat16 l1 = __float2bfloat16(v.y - __bfloat162float(h1));
    __nv_bfloat16 l2 = __float2bfloat16(v.z - __bfloat162float(h2));
    __nv_bfloat16 l3 = __float2bfloat16(v.w - __bfloat162float(h3));
    __nv_bfloat162* ph = (__nv_bfloat162*)(sg.hi + (size_t)i * 4);
    __nv_bfloat162* pl = (__nv_bfloat162*)(sg.lo + (size_t)i * 4);
    ph[0] = __nv_bfloat162(h0, h1); ph[1] = __nv_bfloat162(h2, h3);
    pl[0] = __nv_bfloat162(l0, l1); pl[1] = __nv_bfloat162(l2, l3);
}

// ---------------- LayerNorm --------------------------------------------------
__global__ void ln_kernel(const float* __restrict__ x,
                          const float* __restrict__ w,
                          const float* __restrict__ b) {
    int row = blockIdx.x;
    const float* xr = x + row * DD;
    float s = 0.f, s2 = 0.f;
    for (int i = threadIdx.x; i < DD; i += blockDim.x) {
        float v = xr[i]; s += v; s2 += v * v;
    }
    __shared__ float rs[32], rs2[32];
    for (int o = 16; o; o >>= 1) {
        s  += __shfl_xor_sync(0xffffffffu, s,  o);
        s2 += __shfl_xor_sync(0xffffffffu, s2, o);
    }
    int wr = threadIdx.x >> 5, ln = threadIdx.x & 31;
    if (ln == 0) { rs[wr] = s; rs2[wr] = s2; }
    __syncthreads();
    if (wr == 0) {
        int nw = blockDim.x >> 5;
        s  = (ln < nw) ? rs[ln]  : 0.f;
        s2 = (ln < nw) ? rs2[ln] : 0.f;
        for (int o = 16; o; o >>= 1) {
            s  += __shfl_xor_sync(0xffffffffu, s,  o);
            s2 += __shfl_xor_sync(0xffffffffu, s2, o);
        }
        if (ln == 0) { rs[0] = s; rs2[0] = s2; }
    }
    __syncthreads();
    float mu  = rs[0] / (float)DD;
    float var = rs2[0] / (float)DD - mu * mu;
    float r   = rsqrtf(var + EPSF);
    for (int i = threadIdx.x; i < DD; i += blockDim.x)
        g_xn[row * DD + i] = (xr[i] - mu) * r * w[i] + b[i];
}

// ---------------- causal conv (K=4) + SiLU -----------------------------------
__global__ void conv_kernel(const float* __restrict__ cw,
                            const float* __restrict__ cb) {
    int idx = blockIdx.x * blockDim.x + threadIdx.x;
    int b = idx / PP, p = idx % PP;
    const float* x = g_xt + (size_t)b * PP;
    float s = *cb;
#pragma unroll
    for (int j = 0; j < KW; j++) {
        int src = p + j - (KW - 1);
        if (src >= 0) s += cw[j] * x[src];
    }
    g_xc[idx] = s / (1.f + expf(-s));
}

// ---------------- i_t / f_t ---------------------------------------------------
__global__ void if_kernel(const float* __restrict__ Wi, const float* __restrict__ bi,
                          const float* __restrict__ Wf, const float* __restrict__ bf) {
    int bh = blockIdx.x;
    int b = bh / HH, h = bh % HH;
    int warp = threadIdx.x >> 5, lane = threadIdx.x & 31;
    const float* W = warp ? Wf : Wi;
    const float* xc = g_xc + (size_t)b * PP;
    const float* wr = W + (size_t)h * PP;
    float s = 0.f;
    for (int i = lane; i < PP; i += 32) s += xc[i] * wr[i];
    for (int o = 16; o; o >>= 1) s += __shfl_xor_sync(0xffffffffu, s, o);
    if (lane == 0) {
        if (warp) g_f[bh] = s + bf[h];
        else      g_i[bh] = s + bi[h];
    }
}

// ---------------- cell: gates, c_t, n_t, num/den, o-gate, GroupNorm ----------
__global__ void cell_kernel(const float* __restrict__ c_in,
                            const float* __restrict__ n_in,
                            const float* __restrict__ m_in,
                            const float* __restrict__ gnw,
                            const float* __restrict__ gnb,
                            float* __restrict__ c_out,
                            float* __restrict__ n_out,
                            float* __restrict__ m_out) {
    int bh = blockIdx.x;
    int b = bh >> 3, h = bh & 7;
    __shared__ float sq[HDIM], sk[HDIM], sv[HDIM], sh[HDIM];
    __shared__ float s_red[16];
    __shared__ float s_ig, s_fg, s_den, s_mu, s_rstd;
    int tid = threadIdx.x;
    int warp = tid >> 5, lane = tid & 31;

    if (tid == 0) {
        float it = g_i[bh], ft = g_f[bh], m0 = m_in[bh];
        float mt = fmaxf(ft + m0, it);
        s_ig = expf(it - mt);
        s_fg = expf(ft - mt + m0);
        m_out[bh] = mt;
    }
    if (tid < HDIM) {
        int off = b * HIDD + h * HDIM + tid;
        sq[tid] = g_q[off]; sk[tid] = g_k[off]; sv[tid] = g_v[off];
    }
    __syncthreads();
    float ig = s_ig, fg = s_fg;

    float dp = 0.f;
    if (tid < HDIM) {
        float nt = fg * n_in[(size_t)bh * HDIM + tid] + ig * sk[tid];
        n_out[(size_t)bh * HDIM + tid] = nt;
        dp = nt * sq[tid];
    }
    for (int o = 16; o; o >>= 1) dp += __shfl_xor_sync(0xffffffffu, dp, o);
    if (lane == 0) s_red[warp] = dp;
    __syncthreads();
    if (tid == 0)
        s_den = fmaxf(s_red[0] + s_red[1] + s_red[2] + s_red[3], 1.0f);

    float4 kv = ((const float4*)sk)[lane];
    float4 qv = ((const float4*)sq)[lane];
    size_t base = (size_t)bh * HDIM * HDIM;
    for (int d = warp; d < HDIM; d += 8) {
        const float4* src = (const float4*)(c_in + base + (size_t)d * HDIM);
        float4*       dst = (float4*)(c_out + base + (size_t)d * HDIM);
        float ivd = ig * sv[d];
        float4 c = src[lane];
        float4 nc;
        nc.x = fg * c.x + ivd * kv.x;
        nc.y = fg * c.y + ivd * kv.y;
        nc.z = fg * c.z + ivd * kv.z;
        nc.w = fg * c.w + ivd * kv.w;
        dst[lane] = nc;
        float a = nc.x * qv.x + nc.y * qv.y + nc.z * qv.z + nc.w * qv.w;
        for (int o = 16; o; o >>= 1) a += __shfl_xor_sync(0xffffffffu, a, o);
        if (lane == 0) sh[d] = a;
    }
    __syncthreads();

    float hv = 0.f;
    if (tid < HDIM)
        hv = g_o[b * HIDD + h * HDIM + tid] * sh[tid] / s_den;
    float s1 = hv, s2 = hv * hv;
    for (int o = 16; o; o >>= 1) {
        s1 += __shfl_xor_sync(0xffffffffu, s1, o);
        s2 += __shfl_xor_sync(0xffffffffu, s2, o);
    }
    if (lane == 0) { s_red[warp] = s1; s_red[8 + warp] = s2; }
    __syncthreads();
    if (tid == 0) {
        float m1 = (s_red[0] + s_red[1] + s_red[2] + s_red[3]) / (float)HDIM;
        float m2 = (s_red[8] + s_red[9] + s_red[10] + s_red[11]) / (float)HDIM;
        s_mu = m1;
        s_rstd = rsqrtf(m2 - m1 * m1 + EPSF);
    }
    __syncthreads();
    if (tid < HDIM) {
        int c = h * HDIM + tid;
        g_hn[b * HIDD + c] = (hv - s_mu) * s_rstd * gnw[c] + gnb[c];
    }
}

// ---------------- mix: y = (hn + skip) * silu(r) ------------------------------
__global__ void mix_kernel() {
    int i = blockIdx.x * blockDim.x + threadIdx.x;
    float r = g_rt[i];
    g_y[i] = (g_hn[i] + g_sk[i]) * (r / (1.f + expf(-r)));
}

// ---------------- host ---------------------------------------------------------
static void* sym_addr(const void* sym) {
    void* p = nullptr;
    cudaGetSymbolAddress(&p, sym);
    return p;
}

extern "C" void kernel_launch(void* const* d_in, const int* in_sizes, int n_in,
                              void* d_out, int out_size) {
    const float* seq    = (const float*)d_in[0];
    const float* c_tm1  = (const float*)d_in[1];
    const float* n_tm1  = (const float*)d_in[2];
    const float* m_tm1  = (const float*)d_in[3];
    const float* ln_w   = (const float*)d_in[4];
    const float* ln_b   = (const float*)d_in[5];
    const float* gn_w   = (const float*)d_in[6];
    const float* gn_b   = (const float*)d_in[7];
    const float* up_l_w = (const float*)d_in[8];
    const float* up_l_b = (const float*)d_in[9];
    const float* up_r_w = (const float*)d_in[10];
    const float* up_r_b = (const float*)d_in[11];
    const float* down_w = (const float*)d_in[12];
    const float* down_b = (const float*)d_in[13];
    const float* Wi_w   = (const float*)d_in[14];
    const float* Wi_b   = (const float*)d_in[15];
    const float* Wf_w   = (const float*)d_in[16];
    const float* Wf_b   = (const float*)d_in[17];
    const float* Wo_w   = (const float*)d_in[18];
    const float* Wo_b   = (const float*)d_in[19];
    const float* Wq_w   = (const float*)d_in[20];
    const float* Wq_b   = (const float*)d_in[21];
    const float* Wk_w   = (const float*)d_in[22];
    const float* Wk_b   = (const float*)d_in[23];
    const float* Wv_w   = (const float*)d_in[24];
    const float* Wv_b   = (const float*)d_in[25];
    const float* conv_w = (const float*)d_in[26];
    const float* conv_b = (const float*)d_in[27];
    const float* skip_w = (const float*)d_in[28];

    float* out   = (float*)d_out;
    float* c_out = out + (size_t)BB * DD;
    float* n_out = c_out + (size_t)BB * HH * HDIM * HDIM;
    float* m_out = n_out + (size_t)BB * HH * HDIM;

    float* p_xn = (float*)sym_addr(g_xn);
    float* p_xt = (float*)sym_addr(g_xt);
    float* p_rt = (float*)sym_addr(g_rt);
    float* p_xc = (float*)sym_addr(g_xc);
    float* p_q  = (float*)sym_addr(g_q);
    float* p_k  = (float*)sym_addr(g_k);
    float* p_v  = (float*)sym_addr(g_v);
    float* p_o  = (float*)sym_addr(g_o);
    float* p_sk = (float*)sym_addr(g_sk);
    float* p_y  = (float*)sym_addr(g_y);

    __nv_bfloat16* wh  = (__nv_bfloat16*)sym_addr(g_wh);
    __nv_bfloat16* wl  = (__nv_bfloat16*)sym_addr(g_wl);
    __nv_bfloat16* xnh = (__nv_bfloat16*)sym_addr(g_xnh);
    __nv_bfloat16* xnl = (__nv_bfloat16*)sym_addr(g_xnl);
    __nv_bfloat16* xth = (__nv_bfloat16*)sym_addr(g_xth);
    __nv_bfloat16* xtl = (__nv_bfloat16*)sym_addr(g_xtl);
    __nv_bfloat16* xch = (__nv_bfloat16*)sym_addr(g_xch);
    __nv_bfloat16* xcl = (__nv_bfloat16*)sym_addr(g_xcl);
    __nv_bfloat16* yh  = (__nv_bfloat16*)sym_addr(g_yh);
    __nv_bfloat16* yl  = (__nv_bfloat16*)sym_addr(g_yl);

    cudaFuncSetAttribute(tgemm, cudaFuncAttributeMaxDynamicSharedMemorySize, DYN_SMEM);

    const float kscale = 1.0f / sqrtf((float)HDIM);

    // 1. LayerNorm
    ln_kernel<<<BB, 256>>>(seq, ln_w, ln_b);

    // 2. split all weights
    {
        SArgs a; a.nseg = 8;
        a.s[0] = { up_l_w, wh + OFF_UPL,  wl + OFF_UPL,  2048 };
        a.s[1] = { up_r_w, wh + OFF_UPR,  wl + OFF_UPR,  1024 };
        a.s[2] = { Wq_w,   wh + OFF_Q,    wl + OFF_Q,    2048 };
        a.s[3] = { Wk_w,   wh + OFF_K,    wl + OFF_K,    2048 };
        a.s[4] = { Wv_w,   wh + OFF_V,    wl + OFF_V,    2048 };
        a.s[5] = { Wo_w,   wh + OFF_O,    wl + OFF_O,    2048 };
        a.s[6] = { skip_w, wh + OFF_SKIP, wl + OFF_SKIP, 2048 };
        a.s[7] = { down_w, wh + OFF_DOWN, wl + OFF_DOWN, 1024 };
        split_kernel<<<14336, 256>>>(a);
    }

    // 3. split xn
    {
        SArgs a; a.nseg = 1;
        a.s[0] = { p_xn, xnh, xnl, (BB * DD) / 1024 };
        split_kernel<<<(BB * DD) / 1024, 256>>>(a);
    }

    // 4. stage1 GEMM: up_l, up_r
    {
        TArgs a; a.nseg = 2; a.K = DD;
        a.s[0] = { xnh, xnl, wh + OFF_UPL, wl + OFF_UPL, up_l_b, nullptr, p_xt, 1.f, 0, PP / TBN,   PP   };
        a.s[1] = { xnh, xnl, wh + OFF_UPR, wl + OFF_UPR, up_r_b, nullptr, p_rt, 1.f, 0, HIDD / TBN, HIDD };
        tgemm<<<dim3(PP / TBN + HIDD / TBN, BB / TBM), 256, DYN_SMEM>>>(a);
    }

    // 5. causal conv + SiLU
    conv_kernel<<<(BB * PP) / 256, 256>>>(conv_w, conv_b);

    // 6. split xt, xc
    {
        SArgs a; a.nseg = 2;
        a.s[0] = { p_xt, xth, xtl, (BB * PP) / 1024 };
        a.s[1] = { p_xc, xch, xcl, (BB * PP) / 1024 };
        split_kernel<<<2 * (BB * PP) / 1024, 256>>>(a);
    }

    // 7. stage2 GEMM: q, k, v, o, skip
    {
        TArgs a; a.nseg = 5; a.K = PP;
        a.s[0] = { xch, xcl, wh + OFF_Q,    wl + OFF_Q,    Wq_b,    nullptr, p_q,  1.f,    0, HIDD / TBN, HIDD };
        a.s[1] = { xch, xcl, wh + OFF_K,    wl + OFF_K,    Wk_b,    nullptr, p_k,  kscale, 0, HIDD / TBN, HIDD };
        a.s[2] = { xth, xtl, wh + OFF_V,    wl + OFF_V,    Wv_b,    nullptr, p_v,  1.f,    0, HIDD / TBN, HIDD };
        a.s[3] = { xth, xtl, wh + OFF_O,    wl + OFF_O,    Wo_b,    nullptr, p_o,  1.f,    1, HIDD / TBN, HIDD };
        a.s[4] = { xch, xcl, wh + OFF_SKIP, wl + OFF_SKIP, nullptr, nullptr, p_sk, 1.f,    0, HIDD / TBN, HIDD };
        tgemm<<<dim3(5 * (HIDD / TBN), BB / TBM), 256, DYN_SMEM>>>(a);
    }

    // 8. i/f gates
    if_kernel<<<BB * HH, 64>>>(Wi_w, Wi_b, Wf_w, Wf_b);

    // 9. cell update + groupnorm
    cell_kernel<<<BB * HH, 256>>>(c_tm1, n_tm1, m_tm1, gn_w, gn_b, c_out, n_out, m_out);

    // 10. gated mix
    mix_kernel<<<(BB * HIDD) / 256, 256>>>();

    // 11. split y
    {
        SArgs a; a.nseg = 1;
        a.s[0] = { p_y, yh, yl, (BB * HIDD) / 1024 };
        split_kernel<<<(BB * HIDD) / 1024, 256>>>(a);
    }

    // 12. down projection + bias + residual
    {
        TArgs a; a.nseg = 1; a.K = HIDD;
        a.s[0] = { yh, yl, wh + OFF_DOWN, wl + OFF_DOWN, down_b, seq, out, 1.f, 0, DD / TBN, DD };
        tgemm<<<dim3(DD / TBN, BB / TBM), 256, DYN_SMEM>>>(a);
    }
}